// round 9
// baseline (speedup 1.0000x reference)
#include <cuda_runtime.h>
#include <cuda_fp16.h>
#include <math.h>
#include <stdint.h>

// Problem constants
#define TOK   32768          // B*N = 8*4096
#define NEXP  8
#define DDIM  512
#define BND   16777216       // TOK * DDIM
#define LN_EPS 1e-5f

// GEMM tile config (pure fp16 operands, fp32 accum, fused LN epilogue)
#define BM 64
#define BN 512
#define BK 32
#define NCHUNK (DDIM / BK)   // 16
// smem stage layout (bytes): rows padded to 40 fp16 = 80B (conflict-free ldsm)
#define A_OFF 0
#define B_OFF 5120
#define STAGE_B 46080        // 5120 (A) + 40960 (B)
#define NSTAGE 3
#define SMEM_DYN (NSTAGE * STAGE_B)   // 138240

// ---------------------------------------------------------------------------
// Scratch (__device__ globals; no allocations allowed)
// ---------------------------------------------------------------------------
__device__ int   g_cnt[NEXP];
__device__ int   g_pairTok[NEXP * TOK];
__device__ int   g_tokPair[TOK * 4];
__device__ float g_tokW[TOK * 4];
__device__ __half g_h2[(size_t)NEXP * TOK * DDIM];   // GEMM2 out (POST-LN2), fp16
__device__ float g_part[4096];
__device__ __half g_xh[(size_t)TOK * DDIM];          // x fp16 (token space)
__device__ __half g_ah[(size_t)NEXP * TOK * DDIM];   // GEMM1 out (POST-LN1+relu), fp16
__device__ __half g_w1t[(size_t)NEXP * DDIM * DDIM]; // W1^T fp16
__device__ __half g_w2t[(size_t)NEXP * DDIM * DDIM]; // W2^T fp16

// ---------------------------------------------------------------------------
// Helpers
// ---------------------------------------------------------------------------
__device__ __forceinline__ uint32_t smem_u32(const void* p) {
    uint32_t a;
    asm("{ .reg .u64 t; cvta.to.shared.u64 t, %1; cvt.u32.u64 %0, t; }" : "=r"(a) : "l"(p));
    return a;
}
__device__ __forceinline__ void cp16(uint32_t dst, const void* src) {
    asm volatile("cp.async.cg.shared.global [%0], [%1], 16;" :: "r"(dst), "l"(src));
}
#define CP_COMMIT() asm volatile("cp.async.commit_group;" ::: "memory")
#define CP_WAIT1()  asm volatile("cp.async.wait_group 1;" ::: "memory")
#define CP_WAIT0()  asm volatile("cp.async.wait_group 0;" ::: "memory")
__device__ __forceinline__ void ldsm4(uint32_t* r, uint32_t addr) {
    asm volatile("ldmatrix.sync.aligned.m8n8.x4.shared.b16 {%0,%1,%2,%3}, [%4];"
                 : "=r"(r[0]), "=r"(r[1]), "=r"(r[2]), "=r"(r[3]) : "r"(addr));
}
__device__ __forceinline__ void mma16816(float* c, const uint32_t* a, const uint32_t* b) {
    asm volatile(
        "mma.sync.aligned.m16n8k16.row.col.f32.f16.f16.f32 "
        "{%0,%1,%2,%3}, {%4,%5,%6,%7}, {%8,%9}, {%0,%1,%2,%3};"
        : "+f"(c[0]), "+f"(c[1]), "+f"(c[2]), "+f"(c[3])
        : "r"(a[0]), "r"(a[1]), "r"(a[2]), "r"(a[3]), "r"(b[0]), "r"(b[1]));
}

// ---------------------------------------------------------------------------
// 0) zero counters
// ---------------------------------------------------------------------------
__global__ void init_kernel() {
    if (threadIdx.x < NEXP) g_cnt[threadIdx.x] = 0;
}

// ---------------------------------------------------------------------------
// 1) gating: scores + routing + x fp16 round (token space)
// ---------------------------------------------------------------------------
__global__ void gating_kernel(const float* __restrict__ x,
                              const float* __restrict__ Wg,
                              const float* __restrict__ bg) {
    int gw = (blockIdx.x * blockDim.x + threadIdx.x) >> 5;
    if (gw >= TOK) return;
    int lane = threadIdx.x & 31;
    const float* xr = x + (size_t)gw * DDIM;
    __half* xh = g_xh + (size_t)gw * DDIM;

    float s[NEXP];
#pragma unroll
    for (int e = 0; e < NEXP; e++) s[e] = 0.f;
#pragma unroll
    for (int i = 0; i < 16; i++) {
        int d = lane + i * 32;
        float xv = xr[d];
        const float* wr = Wg + d * NEXP;
#pragma unroll
        for (int e = 0; e < NEXP; e++) s[e] += xv * wr[e];
        xh[d] = __float2half_rn(xv);
    }
#pragma unroll
    for (int e = 0; e < NEXP; e++) {
#pragma unroll
        for (int o = 16; o > 0; o >>= 1)
            s[e] += __shfl_xor_sync(0xffffffffu, s[e], o);
    }
    if (lane == 0) {
#pragma unroll
        for (int e = 0; e < NEXP; e++) s[e] += bg[e];
        int i0 = 0; float v0 = s[0];
        for (int e = 1; e < NEXP; e++) if (s[e] > v0) { v0 = s[e]; i0 = e; }
        int i1 = -1; float v1 = -1e30f;
        for (int e = 0; e < NEXP; e++) if (e != i0 && s[e] > v1) { v1 = s[e]; i1 = e; }
        int j0 = 0; float u0 = s[0];
        for (int e = 1; e < NEXP; e++) if (s[e] < u0) { u0 = s[e]; j0 = e; }
        int j1 = -1; float u1 = 1e30f;
        for (int e = 0; e < NEXP; e++) if (e != j0 && s[e] < u1) { u1 = s[e]; j1 = e; }

        float et  = expf(v1 - v0);
        float wt0 = 1.f / (1.f + et);
        float wt1 = et * wt0;
        float eb  = expf(u0 - u1);
        float wb1 = 1.f / (1.f + eb);
        float wb0 = eb * wb1;

        int p;
        p = atomicAdd(&g_cnt[i0], 1);
        g_pairTok[i0 * TOK + p] = gw;
        g_tokPair[gw * 4 + 0] = i0 * TOK + p;  g_tokW[gw * 4 + 0] = wt0;
        p = atomicAdd(&g_cnt[i1], 1);
        g_pairTok[i1 * TOK + p] = gw;
        g_tokPair[gw * 4 + 1] = i1 * TOK + p;  g_tokW[gw * 4 + 1] = wt1;
        p = atomicAdd(&g_cnt[j0], 1);
        g_pairTok[j0 * TOK + p] = gw;
        g_tokPair[gw * 4 + 2] = j0 * TOK + p;  g_tokW[gw * 4 + 2] = wb0;
        p = atomicAdd(&g_cnt[j1], 1);
        g_pairTok[j1 * TOK + p] = gw;
        g_tokPair[gw * 4 + 3] = j1 * TOK + p;  g_tokW[gw * 4 + 3] = wb1;
    }
}

// ---------------------------------------------------------------------------
// 1b) weight prep: W[e][k][n] fp32 -> Wt[e][n][k] fp16 (transpose + round)
// ---------------------------------------------------------------------------
template <int WHICH>
__global__ void wconv_kernel(const float* __restrict__ W) {
    __shared__ float t[32][33];
    int e  = blockIdx.z;
    int kb = blockIdx.x * 32, nb = blockIdx.y * 32;
    const float* src = W + (size_t)e * DDIM * DDIM;
    int tx = threadIdx.x, ty = threadIdx.y;
#pragma unroll
    for (int r = ty; r < 32; r += 8)
        t[r][tx] = src[(size_t)(kb + r) * DDIM + nb + tx];
    __syncthreads();
    __half* T = (WHICH == 1) ? g_w1t : g_w2t;
#pragma unroll
    for (int r = ty; r < 32; r += 8) {
        float v = t[tx][r];  // = W[kb+tx][nb+r]
        T[((size_t)e * DDIM + (nb + r)) * DDIM + kb + tx] = __float2half_rn(v);
    }
}

// ---------------------------------------------------------------------------
// 2/3) fp16 HMMA GEMM + fused LayerNorm epilogue, cp.async 3-stage pipeline.
//      BM=64, BN=512 (full rows!), BK=32; 8 warps (2 x 4), warp tile 32x128.
//      WHICH=1: A = g_xh gathered via pairTok; LN1+relu -> g_ah (fp16).
//      WHICH=2: A = g_ah pair-space;           LN2      -> g_h2 (fp16).
// ---------------------------------------------------------------------------
template <int WHICH>
__global__ void __launch_bounds__(256, 1) gemm_ln(const float* __restrict__ bias,
                                                  const float* __restrict__ lnw,
                                                  const float* __restrict__ lnb) {
    const int e   = blockIdx.z;
    const int cnt = g_cnt[e];
    const int m0  = blockIdx.y * BM;
    if (m0 >= cnt) return;

    extern __shared__ char dsm[];
    const uint32_t sbase = smem_u32(dsm);
    __shared__ float red_s[BM][4];
    __shared__ float red_q[BM][4];

    const int tid  = threadIdx.x;
    const int wid  = tid >> 5;
    const int lane = tid & 31;

    const __half* wt = (WHICH == 1) ? g_w1t : g_w2t;

    // ---- loader precompute: 9 x 16B segments per thread per stage ----
    const __half* src[9];
    uint32_t dst[9];
#pragma unroll
    for (int j = 0; j < 9; j++) {
        int gid = tid + j * 256;
        if (gid < 256) {                        // A: 64 rows x 4 segs
            int row = gid >> 2, ks = gid & 3;
            int rr = m0 + row; if (rr > cnt - 1) rr = cnt - 1;
            if (WHICH == 1) {
                int tokid = g_pairTok[e * TOK + rr];
                src[j] = g_xh + (size_t)tokid * DDIM + ks * 8;
            } else {
                src[j] = g_ah + ((size_t)e * TOK + rr) * DDIM + ks * 8;
            }
            dst[j] = A_OFF + row * 80 + ks * 16;
        } else {                                // B: 512 rows x 4 segs
            int idx = gid - 256;
            int row = idx >> 2, ks = idx & 3;
            src[j] = wt + ((size_t)e * DDIM + row) * DDIM + ks * 8;
            dst[j] = B_OFF + row * 80 + ks * 16;
        }
    }

    auto issue = [&](int chunk, int s) {
        const int k0 = chunk * BK;
        const uint32_t sb = sbase + s * STAGE_B;
#pragma unroll
        for (int j = 0; j < 9; j++) cp16(sb + dst[j], src[j] + k0);
    };

    // warp layout: warp_m = wid>>2 (32 rows), warp_n = wid&3 (128 cols)
    const int warp_m = wid >> 2;
    const int warp_n = wid & 3;
    const int l15 = lane & 15;
    const uint32_t aoff = (uint32_t)((warp_m * 32 + l15) * 80 + (lane >> 4) * 16);
    const uint32_t boff = (uint32_t)((warp_n * 128 + (lane >> 4) * 8 + (lane & 7)) * 80 +
                                     ((lane >> 3) & 1) * 16);

    float acc[2][16][4];
#pragma unroll
    for (int mt = 0; mt < 2; mt++)
#pragma unroll
        for (int nt = 0; nt < 16; nt++)
#pragma unroll
            for (int q = 0; q < 4; q++) acc[mt][nt][q] = 0.f;

    issue(0, 0); CP_COMMIT();
    issue(1, 1); CP_COMMIT();

    for (int i = 0; i < NCHUNK; i++) {
        const int s = i % NSTAGE;
        CP_WAIT1();
        __syncthreads();
        if (i + 2 < NCHUNK) issue(i + 2, (i + 2) % NSTAGE);
        CP_COMMIT();

        const uint32_t sb = sbase + s * STAGE_B;
        const uint32_t aA = sb + A_OFF + aoff;
        const uint32_t bB = sb + B_OFF + boff;
#pragma unroll
        for (int k16 = 0; k16 < 2; k16++) {
            uint32_t bh[16][2];
#pragma unroll
            for (int p = 0; p < 8; p++) {
                uint32_t r4[4];
                ldsm4(r4, bB + p * 16 * 80 + k16 * 32);
                bh[2 * p][0] = r4[0]; bh[2 * p][1] = r4[1];
                bh[2 * p + 1][0] = r4[2]; bh[2 * p + 1][1] = r4[3];
            }
#pragma unroll
            for (int mt = 0; mt < 2; mt++) {
                uint32_t ah[4];
                ldsm4(ah, aA + mt * 16 * 80 + k16 * 32);
#pragma unroll
                for (int nt = 0; nt < 16; nt++)
                    mma16816(acc[mt][nt], ah, bh[nt]);
            }
        }
    }
    CP_WAIT0();
    __syncthreads();   // stages dead; reuse dsm for epilogue params

    // ---- epilogue: bias + LayerNorm (+relu) + fp16 store ----
    float* sb_bias = (float*)dsm;
    float* sb_w    = (float*)(dsm + 2048);
    float* sb_b    = (float*)(dsm + 4096);
    for (int i = tid; i < DDIM; i += 256) {
        sb_bias[i] = bias[(size_t)e * DDIM + i];
        sb_w[i]    = lnw[(size_t)e * DDIM + i];
        sb_b[i]    = lnb[(size_t)e * DDIM + i];
    }
    __syncthreads();

    const int group = lane >> 2;
    const int t4    = lane & 3;

    // add bias into acc
#pragma unroll
    for (int mt = 0; mt < 2; mt++)
#pragma unroll
        for (int nt = 0; nt < 16; nt++) {
            int col = warp_n * 128 + nt * 8 + t4 * 2;
            float b0 = sb_bias[col], b1 = sb_bias[col + 1];
            acc[mt][nt][0] += b0; acc[mt][nt][1] += b1;
            acc[mt][nt][2] += b0; acc[mt][nt][3] += b1;
        }

    // per-row partial sum/sumsq -> deterministic reduction
#pragma unroll
    for (int mt = 0; mt < 2; mt++) {
        float s0 = 0.f, q0 = 0.f, s1 = 0.f, q1 = 0.f;
#pragma unroll
        for (int nt = 0; nt < 16; nt++) {
            s0 += acc[mt][nt][0] + acc[mt][nt][1];
            q0 += acc[mt][nt][0] * acc[mt][nt][0] + acc[mt][nt][1] * acc[mt][nt][1];
            s1 += acc[mt][nt][2] + acc[mt][nt][3];
            q1 += acc[mt][nt][2] * acc[mt][nt][2] + acc[mt][nt][3] * acc[mt][nt][3];
        }
#pragma unroll
        for (int o = 1; o <= 2; o <<= 1) {
            s0 += __shfl_xor_sync(0xffffffffu, s0, o);
            q0 += __shfl_xor_sync(0xffffffffu, q0, o);
            s1 += __shfl_xor_sync(0xffffffffu, s1, o);
            q1 += __shfl_xor_sync(0xffffffffu, q1, o);
        }
        if (t4 == 0) {
            int r0 = warp_m * 32 + mt * 16 + group;
            red_s[r0][warp_n] = s0;     red_q[r0][warp_n] = q0;
            red_s[r0 + 8][warp_n] = s1; red_q[r0 + 8][warp_n] = q1;
        }
    }
    __syncthreads();

    __half* Out = (WHICH == 1) ? g_ah : g_h2;
#pragma unroll
    for (int mt = 0; mt < 2; mt++) {
#pragma unroll
        for (int h = 0; h < 2; h++) {
            int rloc = warp_m * 32 + mt * 16 + h * 8 + group;
            int r = m0 + rloc;
            if (r >= cnt) continue;
            float ssum = red_s[rloc][0] + red_s[rloc][1] + red_s[rloc][2] + red_s[rloc][3];
            float qsum = red_q[rloc][0] + red_q[rloc][1] + red_q[rloc][2] + red_q[rloc][3];
            float mu = ssum * (1.f / DDIM);
            float var = qsum * (1.f / DDIM) - mu * mu;
            float rstd = rsqrtf(var + LN_EPS);
            __half* orow = Out + ((size_t)e * TOK + r) * DDIM + warp_n * 128 + t4 * 2;
#pragma unroll
            for (int nt = 0; nt < 16; nt++) {
                int col = warp_n * 128 + nt * 8 + t4 * 2;
                float y0 = (acc[mt][nt][2 * h + 0] - mu) * rstd * sb_w[col] + sb_b[col];
                float y1 = (acc[mt][nt][2 * h + 1] - mu) * rstd * sb_w[col + 1] + sb_b[col + 1];
                if (WHICH == 1) { y0 = fmaxf(y0, 0.f); y1 = fmaxf(y1, 0.f); }
                *(__half2*)(orow + nt * 8) = __floats2half2_rn(y0, y1);
            }
        }
    }
}

// ---------------------------------------------------------------------------
// 6) combine: warp per token; 4 post-LN fp16 rows of g_h2, weighted sums
// ---------------------------------------------------------------------------
__global__ void combine_kernel(const float* __restrict__ x,
                               float* __restrict__ out) {
    int gw   = (blockIdx.x * blockDim.x + threadIdx.x) >> 5;
    int lane = threadIdx.x & 31;
    const int t = gw;

    int   pr[4];
    float wt[4];
#pragma unroll
    for (int j = 0; j < 4; j++) {
        pr[j] = g_tokPair[t * 4 + j];
        wt[j] = g_tokW[t * 4 + j];
    }

    const __half2* ra = (const __half2*)(g_h2 + (size_t)pr[0] * DDIM);
    const __half2* rb = (const __half2*)(g_h2 + (size_t)pr[1] * DDIM);
    const __half2* rc = (const __half2*)(g_h2 + (size_t)pr[2] * DDIM);
    const __half2* rd = (const __half2*)(g_h2 + (size_t)pr[3] * DDIM);
    const float* xr = x + (size_t)t * DDIM;
    float* o_out = out + (size_t)t * DDIM;
    float* o_top = out + (size_t)BND + (size_t)t * DDIM;
    float* o_bot = out + 2 * (size_t)BND + (size_t)t * DDIM;

    float accd = 0.f;
#pragma unroll
    for (int i = 0; i < 8; i++) {
        int c = lane + i * 32;
        float2 va = __half22float2(ra[c]);
        float2 vb = __half22float2(rb[c]);
        float2 vc = __half22float2(rc[c]);
        float2 vd = __half22float2(rd[c]);
        float topx = wt[0] * va.x + wt[1] * vb.x;
        float topy = wt[0] * va.y + wt[1] * vb.y;
        float botx = wt[2] * vc.x + wt[3] * vd.x;
        float boty = wt[2] * vc.y + wt[3] * vd.y;
        int d = 2 * c;
        o_top[d] = topx;     o_top[d + 1] = topy;
        o_bot[d] = botx;     o_bot[d + 1] = boty;
        o_out[d] = topx + xr[d];
        o_out[d + 1] = topy + xr[d + 1];
        float dfx = topx - botx, dfy = topy - boty;
        accd += dfx * dfx + dfy * dfy;
    }
#pragma unroll
    for (int o = 16; o > 0; o >>= 1) accd += __shfl_xor_sync(0xffffffffu, accd, o);

    __shared__ float red[8];
    if (lane == 0) red[threadIdx.x >> 5] = accd;
    __syncthreads();
    if (threadIdx.x == 0) {
        float ssum = 0.f;
        for (int i = 0; i < 8; i++) ssum += red[i];
        g_part[blockIdx.x] = ssum;
    }
}

// ---------------------------------------------------------------------------
// 7) loss
// ---------------------------------------------------------------------------
__global__ void loss_kernel(float* __restrict__ out) {
    int w = threadIdx.x >> 5, lane = threadIdx.x & 31;
    __shared__ float lred[8];
    float s = 0.f;
    for (int i = lane; i < 512; i += 32) s += g_part[w * 512 + i];
#pragma unroll
    for (int o = 16; o > 0; o >>= 1) s += __shfl_xor_sync(0xffffffffu, s, o);
    if (lane == 0) lred[w] = 1.f / (sqrtf(s) + 1e-8f);
    __syncthreads();
    if (threadIdx.x == 0) {
        float a = 0.f;
        for (int i = 0; i < 8; i++) a += lred[i];
        out[(size_t)3 * BND] = a * (1.f / 8.f);
    }
}

// ---------------------------------------------------------------------------
// launch
// ---------------------------------------------------------------------------
extern "C" void kernel_launch(void* const* d_in, const int* in_sizes, int n_in,
                              void* d_out, int out_size) {
    const float* x    = (const float*)d_in[0];
    const float* Wg   = (const float*)d_in[1];
    const float* bg   = (const float*)d_in[2];
    const float* W1   = (const float*)d_in[3];
    const float* b1   = (const float*)d_in[4];
    const float* ln1w = (const float*)d_in[5];
    const float* ln1b = (const float*)d_in[6];
    const float* W2   = (const float*)d_in[7];
    const float* b2   = (const float*)d_in[8];
    const float* ln2w = (const float*)d_in[9];
    const float* ln2b = (const float*)d_in[10];
    float* out = (float*)d_out;

    static int smem_set = 0;
    if (!smem_set) {
        cudaFuncSetAttribute(gemm_ln<1>, cudaFuncAttributeMaxDynamicSharedMemorySize, SMEM_DYN);
        cudaFuncSetAttribute(gemm_ln<2>, cudaFuncAttributeMaxDynamicSharedMemorySize, SMEM_DYN);
        smem_set = 1;
    }

    init_kernel<<<1, 32>>>();
    gating_kernel<<<TOK * 32 / 256, 256>>>(x, Wg, bg);

    dim3 wgrid(DDIM / 32, DDIM / 32, NEXP);
    wconv_kernel<1><<<wgrid, dim3(32, 8)>>>(W1);
    wconv_kernel<2><<<wgrid, dim3(32, 8)>>>(W2);

    dim3 ggrid(1, TOK / BM, NEXP);   // (1, 512, 8)
    gemm_ln<1><<<ggrid, 256, SMEM_DYN>>>(b1, ln1w, ln1b);
    gemm_ln<2><<<ggrid, 256, SMEM_DYN>>>(b2, ln2w, ln2b);
    combine_kernel<<<TOK * 32 / 256, 256>>>(x, out);
    loss_kernel<<<1, 256>>>(out);
}

// round 10
// speedup vs baseline: 1.1780x; 1.1780x over previous
#include <cuda_runtime.h>
#include <cuda_fp16.h>
#include <math.h>
#include <stdint.h>

// Problem constants
#define TOK   32768          // B*N = 8*4096
#define NEXP  8
#define DDIM  512
#define BND   16777216       // TOK * DDIM
#define LN_EPS 1e-5f

// GEMM tile config (pure fp16 operands, fp32 accum)
#define BM 128
#define BN 256
#define BK 64
#define NCHUNK (DDIM / BK)   // 8
// smem stage layout (bytes): rows padded to 72 fp16 = 144B (conflict-free ldsm)
#define ROWB 144
#define A_OFF 0
#define B_OFF (BM * ROWB)                 // 18432
#define STAGE_B (B_OFF + BN * ROWB)       // 55296
#define NSTAGE 3
#define SMEM_DYN (NSTAGE * STAGE_B)       // 165888

// ---------------------------------------------------------------------------
// Scratch (__device__ globals; no allocations allowed)
// ---------------------------------------------------------------------------
__device__ int   g_cnt[NEXP];
__device__ int   g_pairTok[NEXP * TOK];
__device__ int   g_tokPair[TOK * 4];
__device__ float g_tokW[TOK * 4];
__device__ __half g_h1[(size_t)NEXP * TOK * DDIM];   // GEMM1 out (pre-LN1), fp16
__device__ __half g_h2[(size_t)NEXP * TOK * DDIM];   // GEMM2 out (pre-LN2), fp16
__device__ float g_part[4096];
__device__ __half g_xh[(size_t)TOK * DDIM];          // x fp16 (token space)
__device__ __half g_ah[(size_t)NEXP * TOK * DDIM];   // ln1 out fp16 (pair space)
__device__ __half g_w1t[(size_t)NEXP * DDIM * DDIM]; // W1^T fp16
__device__ __half g_w2t[(size_t)NEXP * DDIM * DDIM]; // W2^T fp16

// ---------------------------------------------------------------------------
// Helpers
// ---------------------------------------------------------------------------
__device__ __forceinline__ uint32_t smem_u32(const void* p) {
    uint32_t a;
    asm("{ .reg .u64 t; cvta.to.shared.u64 t, %1; cvt.u32.u64 %0, t; }" : "=r"(a) : "l"(p));
    return a;
}
__device__ __forceinline__ void cp16(uint32_t dst, const void* src) {
    asm volatile("cp.async.cg.shared.global [%0], [%1], 16;" :: "r"(dst), "l"(src));
}
#define CP_COMMIT() asm volatile("cp.async.commit_group;" ::: "memory")
#define CP_WAIT1()  asm volatile("cp.async.wait_group 1;" ::: "memory")
__device__ __forceinline__ void ldsm4(uint32_t* r, uint32_t addr) {
    asm volatile("ldmatrix.sync.aligned.m8n8.x4.shared.b16 {%0,%1,%2,%3}, [%4];"
                 : "=r"(r[0]), "=r"(r[1]), "=r"(r[2]), "=r"(r[3]) : "r"(addr));
}
__device__ __forceinline__ void mma16816(float* c, const uint32_t* a, const uint32_t* b) {
    asm volatile(
        "mma.sync.aligned.m16n8k16.row.col.f32.f16.f16.f32 "
        "{%0,%1,%2,%3}, {%4,%5,%6,%7}, {%8,%9}, {%0,%1,%2,%3};"
        : "+f"(c[0]), "+f"(c[1]), "+f"(c[2]), "+f"(c[3])
        : "r"(a[0]), "r"(a[1]), "r"(a[2]), "r"(a[3]), "r"(b[0]), "r"(b[1]));
}

// ---------------------------------------------------------------------------
// 0) zero counters
// ---------------------------------------------------------------------------
__global__ void init_kernel() {
    if (threadIdx.x < NEXP) g_cnt[threadIdx.x] = 0;
}

// ---------------------------------------------------------------------------
// 1) gating: scores + routing + x fp16 round (token space)
// ---------------------------------------------------------------------------
__global__ void gating_kernel(const float* __restrict__ x,
                              const float* __restrict__ Wg,
                              const float* __restrict__ bg) {
    int gw = (blockIdx.x * blockDim.x + threadIdx.x) >> 5;
    if (gw >= TOK) return;
    int lane = threadIdx.x & 31;
    const float* xr = x + (size_t)gw * DDIM;
    __half* xh = g_xh + (size_t)gw * DDIM;

    float s[NEXP];
#pragma unroll
    for (int e = 0; e < NEXP; e++) s[e] = 0.f;
#pragma unroll
    for (int i = 0; i < 16; i++) {
        int d = lane + i * 32;
        float xv = xr[d];
        const float* wr = Wg + d * NEXP;
#pragma unroll
        for (int e = 0; e < NEXP; e++) s[e] += xv * wr[e];
        xh[d] = __float2half_rn(xv);
    }
#pragma unroll
    for (int e = 0; e < NEXP; e++) {
#pragma unroll
        for (int o = 16; o > 0; o >>= 1)
            s[e] += __shfl_xor_sync(0xffffffffu, s[e], o);
    }
    if (lane == 0) {
#pragma unroll
        for (int e = 0; e < NEXP; e++) s[e] += bg[e];
        int i0 = 0; float v0 = s[0];
        for (int e = 1; e < NEXP; e++) if (s[e] > v0) { v0 = s[e]; i0 = e; }
        int i1 = -1; float v1 = -1e30f;
        for (int e = 0; e < NEXP; e++) if (e != i0 && s[e] > v1) { v1 = s[e]; i1 = e; }
        int j0 = 0; float u0 = s[0];
        for (int e = 1; e < NEXP; e++) if (s[e] < u0) { u0 = s[e]; j0 = e; }
        int j1 = -1; float u1 = 1e30f;
        for (int e = 0; e < NEXP; e++) if (e != j0 && s[e] < u1) { u1 = s[e]; j1 = e; }

        float et  = expf(v1 - v0);
        float wt0 = 1.f / (1.f + et);
        float wt1 = et * wt0;
        float eb  = expf(u0 - u1);
        float wb1 = 1.f / (1.f + eb);
        float wb0 = eb * wb1;

        int p;
        p = atomicAdd(&g_cnt[i0], 1);
        g_pairTok[i0 * TOK + p] = gw;
        g_tokPair[gw * 4 + 0] = i0 * TOK + p;  g_tokW[gw * 4 + 0] = wt0;
        p = atomicAdd(&g_cnt[i1], 1);
        g_pairTok[i1 * TOK + p] = gw;
        g_tokPair[gw * 4 + 1] = i1 * TOK + p;  g_tokW[gw * 4 + 1] = wt1;
        p = atomicAdd(&g_cnt[j0], 1);
        g_pairTok[j0 * TOK + p] = gw;
        g_tokPair[gw * 4 + 2] = j0 * TOK + p;  g_tokW[gw * 4 + 2] = wb0;
        p = atomicAdd(&g_cnt[j1], 1);
        g_pairTok[j1 * TOK + p] = gw;
        g_tokPair[gw * 4 + 3] = j1 * TOK + p;  g_tokW[gw * 4 + 3] = wb1;
    }
}

// ---------------------------------------------------------------------------
// 1b) weight prep: W[e][k][n] fp32 -> Wt[e][n][k] fp16 (transpose + round)
// ---------------------------------------------------------------------------
template <int WHICH>
__global__ void wconv_kernel(const float* __restrict__ W) {
    __shared__ float t[32][33];
    int e  = blockIdx.z;
    int kb = blockIdx.x * 32, nb = blockIdx.y * 32;
    const float* src = W + (size_t)e * DDIM * DDIM;
    int tx = threadIdx.x, ty = threadIdx.y;
#pragma unroll
    for (int r = ty; r < 32; r += 8)
        t[r][tx] = src[(size_t)(kb + r) * DDIM + nb + tx];
    __syncthreads();
    __half* T = (WHICH == 1) ? g_w1t : g_w2t;
#pragma unroll
    for (int r = ty; r < 32; r += 8) {
        float v = t[tx][r];  // = W[kb+tx][nb+r]
        T[((size_t)e * DDIM + (nb + r)) * DDIM + kb + tx] = __float2half_rn(v);
    }
}

// ---------------------------------------------------------------------------
// 2/4) fp16 HMMA GEMM, cp.async 3-stage pipeline, BK=64.
//      BM=128, BN=256; 256 threads = 8 warps (2 x 4), warp tile 64x64.
//      WHICH=1: A = g_xh gathered via pairTok; out g_h1 (fp16).
//      WHICH=2: A = g_ah pair-space (ln1 out); out g_h2 (fp16).
// ---------------------------------------------------------------------------
template <int WHICH>
__global__ void __launch_bounds__(256, 1) gemm_mma(const float* __restrict__ bias) {
    const int e   = blockIdx.z;
    const int cnt = g_cnt[e];
    const int m0  = blockIdx.y * BM;
    if (m0 >= cnt) return;
    const int n0  = blockIdx.x * BN;

    extern __shared__ char dsm[];
    const uint32_t sbase = smem_u32(dsm);

    const int tid  = threadIdx.x;
    const int wid  = tid >> 5;
    const int lane = tid & 31;

    const __half* wt = (WHICH == 1) ? g_w1t : g_w2t;

    // ---- loader precompute: 12 x 16B segments per thread per stage ----
    // A: 128 rows x 8 segs (gid 0..1023); B: 256 rows x 8 segs (gid 1024..3071)
    const __half* src[12];
    uint32_t dst[12];
#pragma unroll
    for (int j = 0; j < 12; j++) {
        int gid = tid + j * 256;
        if (gid < 1024) {
            int row = gid >> 3, ks = gid & 7;
            int rr = m0 + row; if (rr > cnt - 1) rr = cnt - 1;
            if (WHICH == 1) {
                int tokid = g_pairTok[e * TOK + rr];
                src[j] = g_xh + (size_t)tokid * DDIM + ks * 8;
            } else {
                src[j] = g_ah + ((size_t)e * TOK + rr) * DDIM + ks * 8;
            }
            dst[j] = A_OFF + row * ROWB + ks * 16;
        } else {
            int idx = gid - 1024;
            int row = idx >> 3, ks = idx & 7;
            src[j] = wt + ((size_t)e * DDIM + n0 + row) * DDIM + ks * 8;
            dst[j] = B_OFF + row * ROWB + ks * 16;
        }
    }

    auto issue = [&](int chunk, int s) {
        const int k0 = chunk * BK;
        const uint32_t sb = sbase + s * STAGE_B;
#pragma unroll
        for (int j = 0; j < 12; j++) cp16(sb + dst[j], src[j] + k0);
    };

    // warp layout: warp_m = wid>>2 (64 rows), warp_n = wid&3 (64 cols)
    const int warp_m = wid >> 2;
    const int warp_n = wid & 3;
    const int l15 = lane & 15;
    const uint32_t aoff = (uint32_t)((warp_m * 64 + l15) * ROWB + (lane >> 4) * 16);
    const uint32_t boff = (uint32_t)((warp_n * 64 + (lane >> 4) * 8 + (lane & 7)) * ROWB +
                                     ((lane >> 3) & 1) * 16);

    float acc[4][8][4];
#pragma unroll
    for (int mt = 0; mt < 4; mt++)
#pragma unroll
        for (int nt = 0; nt < 8; nt++)
#pragma unroll
            for (int q = 0; q < 4; q++) acc[mt][nt][q] = 0.f;

    issue(0, 0); CP_COMMIT();
    issue(1, 1); CP_COMMIT();

    for (int i = 0; i < NCHUNK; i++) {
        const int s = i % NSTAGE;
        CP_WAIT1();
        __syncthreads();
        if (i + 2 < NCHUNK) issue(i + 2, (i + 2) % NSTAGE);
        CP_COMMIT();

        const uint32_t sb = sbase + s * STAGE_B;
        const uint32_t aA = sb + A_OFF + aoff;
        const uint32_t bB = sb + B_OFF + boff;
#pragma unroll
        for (int k16 = 0; k16 < 4; k16++) {
            uint32_t bh[8][2];
#pragma unroll
            for (int p = 0; p < 4; p++) {
                uint32_t r4[4];
                ldsm4(r4, bB + p * 16 * ROWB + k16 * 32);
                bh[2 * p][0] = r4[0]; bh[2 * p][1] = r4[1];
                bh[2 * p + 1][0] = r4[2]; bh[2 * p + 1][1] = r4[3];
            }
#pragma unroll
            for (int mt = 0; mt < 4; mt++) {
                uint32_t ah[4];
                ldsm4(ah, aA + mt * 16 * ROWB + k16 * 32);
#pragma unroll
                for (int nt = 0; nt < 8; nt++)
                    mma16816(acc[mt][nt], ah, bh[nt]);
            }
        }
    }

    // ---- epilogue: bias add + fp16 store ----
    const int groupid = lane >> 2;
    const int t4      = lane & 3;
    float2 bv[8];
#pragma unroll
    for (int nt = 0; nt < 8; nt++)
        bv[nt] = *(const float2*)(bias + (size_t)e * DDIM + n0 + warp_n * 64 + nt * 8 + t4 * 2);

    __half* OutB = (WHICH == 1) ? g_h1 : g_h2;
#pragma unroll
    for (int mt = 0; mt < 4; mt++) {
        int r0 = m0 + warp_m * 64 + mt * 16 + groupid;
        int r1 = r0 + 8;
        __half* p0 = OutB + ((size_t)e * TOK + r0) * DDIM + n0 + warp_n * 64 + t4 * 2;
        __half* p1 = OutB + ((size_t)e * TOK + r1) * DDIM + n0 + warp_n * 64 + t4 * 2;
#pragma unroll
        for (int nt = 0; nt < 8; nt++) {
            if (r0 < cnt)
                *(__half2*)(p0 + nt * 8) =
                    __floats2half2_rn(acc[mt][nt][0] + bv[nt].x, acc[mt][nt][1] + bv[nt].y);
            if (r1 < cnt)
                *(__half2*)(p1 + nt * 8) =
                    __floats2half2_rn(acc[mt][nt][2] + bv[nt].x, acc[mt][nt][3] + bv[nt].y);
        }
    }
}

// ---------------------------------------------------------------------------
// 3) LN1 + relu: reads g_h1 fp16, writes fp16 into g_ah
// ---------------------------------------------------------------------------
__global__ void ln1_kernel(const float* __restrict__ w,
                           const float* __restrict__ b) {
    int gw = (blockIdx.x * blockDim.x + threadIdx.x) >> 5;
    int e   = gw >> 15;
    int pos = gw & (TOK - 1);
    if (pos >= g_cnt[e]) return;
    int lane = threadIdx.x & 31;
    const __half2* row = (const __half2*)(g_h1 + (size_t)gw * DDIM);

    float2 v[8];
    float s = 0.f;
#pragma unroll
    for (int i = 0; i < 8; i++) {
        v[i] = __half22float2(row[lane + i * 32]);
        s += v[i].x + v[i].y;
    }
#pragma unroll
    for (int o = 16; o > 0; o >>= 1) s += __shfl_xor_sync(0xffffffffu, s, o);
    float mu = s * (1.f / DDIM);

    float q = 0.f;
#pragma unroll
    for (int i = 0; i < 8; i++) {
        float dx = v[i].x - mu, dy = v[i].y - mu;
        q += dx * dx + dy * dy;
    }
#pragma unroll
    for (int o = 16; o > 0; o >>= 1) q += __shfl_xor_sync(0xffffffffu, q, o);
    float rstd = rsqrtf(q * (1.f / DDIM) + LN_EPS);

    const float* we = w + e * DDIM;
    const float* be = b + e * DDIM;
    __half* oh = g_ah + (size_t)gw * DDIM;
#pragma unroll
    for (int i = 0; i < 8; i++) {
        int d = 2 * (lane + i * 32);
        float yx = fmaxf((v[i].x - mu) * rstd * we[d] + be[d], 0.f);
        float yy = fmaxf((v[i].y - mu) * rstd * we[d + 1] + be[d + 1], 0.f);
        *(__half2*)(oh + d) = __floats2half2_rn(yx, yy);
    }
}

// ---------------------------------------------------------------------------
// 6) combine + fused LN2: warp per token; 4 fp16 rows of g_h2 (pre-LN)
// ---------------------------------------------------------------------------
__global__ void combine_kernel(const float* __restrict__ x,
                               const float* __restrict__ lnw,
                               const float* __restrict__ lnb,
                               float* __restrict__ out) {
    int gw   = (blockIdx.x * blockDim.x + threadIdx.x) >> 5;
    int lane = threadIdx.x & 31;
    const int t = gw;

    int   pr[4];
    float wt[4];
#pragma unroll
    for (int j = 0; j < 4; j++) {
        pr[j] = g_tokPair[t * 4 + j];
        wt[j] = g_tokW[t * 4 + j];
    }

    float2 v[4][8];
    float mu[4], rs[4];
#pragma unroll
    for (int r = 0; r < 4; r++) {
        const __half2* row = (const __half2*)(g_h2 + (size_t)pr[r] * DDIM);
        float s = 0.f;
#pragma unroll
        for (int i = 0; i < 8; i++) {
            v[r][i] = __half22float2(row[lane + i * 32]);
            s += v[r][i].x + v[r][i].y;
        }
#pragma unroll
        for (int o = 16; o > 0; o >>= 1) s += __shfl_xor_sync(0xffffffffu, s, o);
        mu[r] = s * (1.f / DDIM);
        float q = 0.f;
#pragma unroll
        for (int i = 0; i < 8; i++) {
            float dx = v[r][i].x - mu[r], dy = v[r][i].y - mu[r];
            q += dx * dx + dy * dy;
        }
#pragma unroll
        for (int o = 16; o > 0; o >>= 1) q += __shfl_xor_sync(0xffffffffu, q, o);
        rs[r] = rsqrtf(q * (1.f / DDIM) + LN_EPS);
    }

    const float* lw[4];
    const float* lb[4];
#pragma unroll
    for (int r = 0; r < 4; r++) {
        int e = pr[r] >> 15;           // / TOK
        lw[r] = lnw + (size_t)e * DDIM;
        lb[r] = lnb + (size_t)e * DDIM;
    }

    const float* xr = x + (size_t)t * DDIM;
    float* o_out = out + (size_t)t * DDIM;
    float* o_top = out + (size_t)BND + (size_t)t * DDIM;
    float* o_bot = out + 2 * (size_t)BND + (size_t)t * DDIM;

    float accd = 0.f;
#pragma unroll
    for (int i = 0; i < 8; i++) {
        int d = 2 * (lane + i * 32);
#pragma unroll
        for (int h = 0; h < 2; h++) {
            int dd = d + h;
            float va = h ? v[0][i].y : v[0][i].x;
            float vb = h ? v[1][i].y : v[1][i].x;
            float vc = h ? v[2][i].y : v[2][i].x;
            float vd = h ? v[3][i].y : v[3][i].x;
            float ya = (va - mu[0]) * rs[0] * lw[0][dd] + lb[0][dd];
            float yb = (vb - mu[1]) * rs[1] * lw[1][dd] + lb[1][dd];
            float yc = (vc - mu[2]) * rs[2] * lw[2][dd] + lb[2][dd];
            float yd = (vd - mu[3]) * rs[3] * lw[3][dd] + lb[3][dd];
            float top = wt[0] * ya + wt[1] * yb;
            float bot = wt[2] * yc + wt[3] * yd;
            o_top[dd] = top;
            o_bot[dd] = bot;
            o_out[dd] = top + xr[dd];
            float df = top - bot;
            accd += df * df;
        }
    }
#pragma unroll
    for (int o = 16; o > 0; o >>= 1) accd += __shfl_xor_sync(0xffffffffu, accd, o);

    __shared__ float red[8];
    if (lane == 0) red[threadIdx.x >> 5] = accd;
    __syncthreads();
    if (threadIdx.x == 0) {
        float ssum = 0.f;
        for (int i = 0; i < 8; i++) ssum += red[i];
        g_part[blockIdx.x] = ssum;
    }
}

// ---------------------------------------------------------------------------
// 7) loss
// ---------------------------------------------------------------------------
__global__ void loss_kernel(float* __restrict__ out) {
    int w = threadIdx.x >> 5, lane = threadIdx.x & 31;
    __shared__ float lred[8];
    float s = 0.f;
    for (int i = lane; i < 512; i += 32) s += g_part[w * 512 + i];
#pragma unroll
    for (int o = 16; o > 0; o >>= 1) s += __shfl_xor_sync(0xffffffffu, s, o);
    if (lane == 0) lred[w] = 1.f / (sqrtf(s) + 1e-8f);
    __syncthreads();
    if (threadIdx.x == 0) {
        float a = 0.f;
        for (int i = 0; i < 8; i++) a += lred[i];
        out[(size_t)3 * BND] = a * (1.f / 8.f);
    }
}

// ---------------------------------------------------------------------------
// launch
// ---------------------------------------------------------------------------
extern "C" void kernel_launch(void* const* d_in, const int* in_sizes, int n_in,
                              void* d_out, int out_size) {
    const float* x    = (const float*)d_in[0];
    const float* Wg   = (const float*)d_in[1];
    const float* bg   = (const float*)d_in[2];
    const float* W1   = (const float*)d_in[3];
    const float* b1   = (const float*)d_in[4];
    const float* ln1w = (const float*)d_in[5];
    const float* ln1b = (const float*)d_in[6];
    const float* W2   = (const float*)d_in[7];
    const float* b2   = (const float*)d_in[8];
    const float* ln2w = (const float*)d_in[9];
    const float* ln2b = (const float*)d_in[10];
    float* out = (float*)d_out;

    static int smem_set = 0;
    if (!smem_set) {
        cudaFuncSetAttribute(gemm_mma<1>, cudaFuncAttributeMaxDynamicSharedMemorySize, SMEM_DYN);
        cudaFuncSetAttribute(gemm_mma<2>, cudaFuncAttributeMaxDynamicSharedMemorySize, SMEM_DYN);
        smem_set = 1;
    }

    init_kernel<<<1, 32>>>();
    gating_kernel<<<TOK * 32 / 256, 256>>>(x, Wg, bg);

    dim3 wgrid(DDIM / 32, DDIM / 32, NEXP);
    wconv_kernel<1><<<wgrid, dim3(32, 8)>>>(W1);
    wconv_kernel<2><<<wgrid, dim3(32, 8)>>>(W2);

    dim3 ggrid(DDIM / BN, TOK / BM, NEXP);   // (2, 256, 8)
    gemm_mma<1><<<ggrid, 256, SMEM_DYN>>>(b1);
    ln1_kernel<<<NEXP * TOK * 32 / 256, 256>>>(ln1w, ln1b);
    gemm_mma<2><<<ggrid, 256, SMEM_DYN>>>(b2);
    combine_kernel<<<TOK * 32 / 256, 256>>>(x, ln2w, ln2b, out);
    loss_kernel<<<1, 256>>>(out);
}

// round 11
// speedup vs baseline: 1.1903x; 1.0105x over previous
#include <cuda_runtime.h>
#include <cuda_fp16.h>
#include <math.h>
#include <stdint.h>

// Problem constants
#define TOK   32768          // B*N = 8*4096
#define NEXP  8
#define DDIM  512
#define BND   16777216       // TOK * DDIM
#define LN_EPS 1e-5f

// GEMM tile config (pure fp16 operands, fp32 accum)
#define BM 128
#define BN 256
#define BK 64
#define NCHUNK (DDIM / BK)   // 8
// smem stage layout (bytes): rows padded to 72 fp16 = 144B (conflict-free ldsm)
#define ROWB 144
#define A_OFF 0
#define B_OFF (BM * ROWB)                 // 18432
#define STAGE_B (B_OFF + BN * ROWB)       // 55296
#define NSTAGE 4
#define SMEM_DYN (NSTAGE * STAGE_B)       // 221184

// ---------------------------------------------------------------------------
// Scratch (__device__ globals; no allocations allowed)
// ---------------------------------------------------------------------------
__device__ int   g_cnt[NEXP];
__device__ int   g_pairTok[NEXP * TOK];
__device__ int   g_tokPair[TOK * 4];
__device__ float g_tokW[TOK * 4];
__device__ __half g_h1[(size_t)NEXP * TOK * DDIM];   // GEMM1 out (pre-LN1), fp16
__device__ __half g_h2[(size_t)NEXP * TOK * DDIM];   // GEMM2 out (pre-LN2), fp16
__device__ float g_part[4096];
__device__ __half g_xh[(size_t)TOK * DDIM];          // x fp16 (token space)
__device__ __half g_ah[(size_t)NEXP * TOK * DDIM];   // ln1 out fp16 (pair space)
__device__ __half g_w1t[(size_t)NEXP * DDIM * DDIM]; // W1^T fp16
__device__ __half g_w2t[(size_t)NEXP * DDIM * DDIM]; // W2^T fp16

// ---------------------------------------------------------------------------
// Helpers
// ---------------------------------------------------------------------------
__device__ __forceinline__ uint32_t smem_u32(const void* p) {
    uint32_t a;
    asm("{ .reg .u64 t; cvta.to.shared.u64 t, %1; cvt.u32.u64 %0, t; }" : "=r"(a) : "l"(p));
    return a;
}
__device__ __forceinline__ void cp16(uint32_t dst, const void* src) {
    asm volatile("cp.async.cg.shared.global [%0], [%1], 16;" :: "r"(dst), "l"(src));
}
#define CP_COMMIT() asm volatile("cp.async.commit_group;" ::: "memory")
#define CP_WAIT2()  asm volatile("cp.async.wait_group 2;" ::: "memory")
__device__ __forceinline__ void ldsm4(uint32_t* r, uint32_t addr) {
    asm volatile("ldmatrix.sync.aligned.m8n8.x4.shared.b16 {%0,%1,%2,%3}, [%4];"
                 : "=r"(r[0]), "=r"(r[1]), "=r"(r[2]), "=r"(r[3]) : "r"(addr));
}
__device__ __forceinline__ void mma16816(float* c, const uint32_t* a, const uint32_t* b) {
    asm volatile(
        "mma.sync.aligned.m16n8k16.row.col.f32.f16.f16.f32 "
        "{%0,%1,%2,%3}, {%4,%5,%6,%7}, {%8,%9}, {%0,%1,%2,%3};"
        : "+f"(c[0]), "+f"(c[1]), "+f"(c[2]), "+f"(c[3])
        : "r"(a[0]), "r"(a[1]), "r"(a[2]), "r"(a[3]), "r"(b[0]), "r"(b[1]));
}

// ---------------------------------------------------------------------------
// 0) zero counters
// ---------------------------------------------------------------------------
__global__ void init_kernel() {
    if (threadIdx.x < NEXP) g_cnt[threadIdx.x] = 0;
}

// ---------------------------------------------------------------------------
// 1) gating: scores + routing + x fp16 round (token space)
// ---------------------------------------------------------------------------
__global__ void gating_kernel(const float* __restrict__ x,
                              const float* __restrict__ Wg,
                              const float* __restrict__ bg) {
    int gw = (blockIdx.x * blockDim.x + threadIdx.x) >> 5;
    if (gw >= TOK) return;
    int lane = threadIdx.x & 31;
    const float* xr = x + (size_t)gw * DDIM;
    __half* xh = g_xh + (size_t)gw * DDIM;

    float s[NEXP];
#pragma unroll
    for (int e = 0; e < NEXP; e++) s[e] = 0.f;
#pragma unroll
    for (int i = 0; i < 16; i++) {
        int d = lane + i * 32;
        float xv = xr[d];
        const float* wr = Wg + d * NEXP;
#pragma unroll
        for (int e = 0; e < NEXP; e++) s[e] += xv * wr[e];
        xh[d] = __float2half_rn(xv);
    }
#pragma unroll
    for (int e = 0; e < NEXP; e++) {
#pragma unroll
        for (int o = 16; o > 0; o >>= 1)
            s[e] += __shfl_xor_sync(0xffffffffu, s[e], o);
    }
    if (lane == 0) {
#pragma unroll
        for (int e = 0; e < NEXP; e++) s[e] += bg[e];
        int i0 = 0; float v0 = s[0];
        for (int e = 1; e < NEXP; e++) if (s[e] > v0) { v0 = s[e]; i0 = e; }
        int i1 = -1; float v1 = -1e30f;
        for (int e = 0; e < NEXP; e++) if (e != i0 && s[e] > v1) { v1 = s[e]; i1 = e; }
        int j0 = 0; float u0 = s[0];
        for (int e = 1; e < NEXP; e++) if (s[e] < u0) { u0 = s[e]; j0 = e; }
        int j1 = -1; float u1 = 1e30f;
        for (int e = 0; e < NEXP; e++) if (e != j0 && s[e] < u1) { u1 = s[e]; j1 = e; }

        float et  = expf(v1 - v0);
        float wt0 = 1.f / (1.f + et);
        float wt1 = et * wt0;
        float eb  = expf(u0 - u1);
        float wb1 = 1.f / (1.f + eb);
        float wb0 = eb * wb1;

        int p;
        p = atomicAdd(&g_cnt[i0], 1);
        g_pairTok[i0 * TOK + p] = gw;
        g_tokPair[gw * 4 + 0] = i0 * TOK + p;  g_tokW[gw * 4 + 0] = wt0;
        p = atomicAdd(&g_cnt[i1], 1);
        g_pairTok[i1 * TOK + p] = gw;
        g_tokPair[gw * 4 + 1] = i1 * TOK + p;  g_tokW[gw * 4 + 1] = wt1;
        p = atomicAdd(&g_cnt[j0], 1);
        g_pairTok[j0 * TOK + p] = gw;
        g_tokPair[gw * 4 + 2] = j0 * TOK + p;  g_tokW[gw * 4 + 2] = wb0;
        p = atomicAdd(&g_cnt[j1], 1);
        g_pairTok[j1 * TOK + p] = gw;
        g_tokPair[gw * 4 + 3] = j1 * TOK + p;  g_tokW[gw * 4 + 3] = wb1;
    }
}

// ---------------------------------------------------------------------------
// 1b) weight prep (merged W1+W2): W[e][k][n] fp32 -> Wt[e][n][k] fp16
//     blockIdx.z in [0,16): low 3 bits = expert, bit 3 = which matrix
// ---------------------------------------------------------------------------
__global__ void wconv_kernel(const float* __restrict__ W1,
                             const float* __restrict__ W2) {
    __shared__ float t[32][33];
    int z = blockIdx.z;
    int e = z & 7;
    int which = z >> 3;
    const float* W = which ? W2 : W1;
    __half* T = which ? g_w2t : g_w1t;
    int kb = blockIdx.x * 32, nb = blockIdx.y * 32;
    const float* src = W + (size_t)e * DDIM * DDIM;
    int tx = threadIdx.x, ty = threadIdx.y;
#pragma unroll
    for (int r = ty; r < 32; r += 8)
        t[r][tx] = src[(size_t)(kb + r) * DDIM + nb + tx];
    __syncthreads();
#pragma unroll
    for (int r = ty; r < 32; r += 8) {
        float v = t[tx][r];  // = W[kb+tx][nb+r]
        T[((size_t)e * DDIM + (nb + r)) * DDIM + kb + tx] = __float2half_rn(v);
    }
}

// ---------------------------------------------------------------------------
// 2/4) fp16 HMMA GEMM, cp.async 4-stage pipeline, BK=64.
//      BM=128, BN=256; 256 threads = 8 warps (2 x 4), warp tile 64x64.
//      WHICH=1: A = g_xh gathered via pairTok; out g_h1 (fp16).
//      WHICH=2: A = g_ah pair-space (ln1 out); out g_h2 (fp16).
// ---------------------------------------------------------------------------
template <int WHICH>
__global__ void __launch_bounds__(256, 1) gemm_mma(const float* __restrict__ bias) {
    const int e   = blockIdx.z;
    const int cnt = g_cnt[e];
    const int m0  = blockIdx.y * BM;
    if (m0 >= cnt) return;
    const int n0  = blockIdx.x * BN;

    extern __shared__ char dsm[];
    const uint32_t sbase = smem_u32(dsm);

    const int tid  = threadIdx.x;
    const int wid  = tid >> 5;
    const int lane = tid & 31;

    const __half* wt = (WHICH == 1) ? g_w1t : g_w2t;

    // ---- loader precompute: 12 x 16B segments per thread per stage ----
    const __half* src[12];
    uint32_t dst[12];
#pragma unroll
    for (int j = 0; j < 12; j++) {
        int gid = tid + j * 256;
        if (gid < 1024) {
            int row = gid >> 3, ks = gid & 7;
            int rr = m0 + row; if (rr > cnt - 1) rr = cnt - 1;
            if (WHICH == 1) {
                int tokid = g_pairTok[e * TOK + rr];
                src[j] = g_xh + (size_t)tokid * DDIM + ks * 8;
            } else {
                src[j] = g_ah + ((size_t)e * TOK + rr) * DDIM + ks * 8;
            }
            dst[j] = A_OFF + row * ROWB + ks * 16;
        } else {
            int idx = gid - 1024;
            int row = idx >> 3, ks = idx & 7;
            src[j] = wt + ((size_t)e * DDIM + n0 + row) * DDIM + ks * 8;
            dst[j] = B_OFF + row * ROWB + ks * 16;
        }
    }

    auto issue = [&](int chunk, int s) {
        const int k0 = chunk * BK;
        const uint32_t sb = sbase + s * STAGE_B;
#pragma unroll
        for (int j = 0; j < 12; j++) cp16(sb + dst[j], src[j] + k0);
    };

    // warp layout: warp_m = wid>>2 (64 rows), warp_n = wid&3 (64 cols)
    const int warp_m = wid >> 2;
    const int warp_n = wid & 3;
    const int l15 = lane & 15;
    const uint32_t aoff = (uint32_t)((warp_m * 64 + l15) * ROWB + (lane >> 4) * 16);
    const uint32_t boff = (uint32_t)((warp_n * 64 + (lane >> 4) * 8 + (lane & 7)) * ROWB +
                                     ((lane >> 3) & 1) * 16);

    float acc[4][8][4];
#pragma unroll
    for (int mt = 0; mt < 4; mt++)
#pragma unroll
        for (int nt = 0; nt < 8; nt++)
#pragma unroll
            for (int q = 0; q < 4; q++) acc[mt][nt][q] = 0.f;

    issue(0, 0); CP_COMMIT();
    issue(1, 1); CP_COMMIT();
    issue(2, 2); CP_COMMIT();

    for (int i = 0; i < NCHUNK; i++) {
        const int s = i % NSTAGE;
        CP_WAIT2();          // oldest outstanding group (chunk i) complete
        __syncthreads();
        if (i + 3 < NCHUNK) issue(i + 3, (i + 3) % NSTAGE);
        CP_COMMIT();

        const uint32_t sb = sbase + s * STAGE_B;
        const uint32_t aA = sb + A_OFF + aoff;
        const uint32_t bB = sb + B_OFF + boff;
#pragma unroll
        for (int k16 = 0; k16 < 4; k16++) {
            uint32_t bh[8][2];
#pragma unroll
            for (int p = 0; p < 4; p++) {
                uint32_t r4[4];
                ldsm4(r4, bB + p * 16 * ROWB + k16 * 32);
                bh[2 * p][0] = r4[0]; bh[2 * p][1] = r4[1];
                bh[2 * p + 1][0] = r4[2]; bh[2 * p + 1][1] = r4[3];
            }
#pragma unroll
            for (int mt = 0; mt < 4; mt++) {
                uint32_t ah[4];
                ldsm4(ah, aA + mt * 16 * ROWB + k16 * 32);
#pragma unroll
                for (int nt = 0; nt < 8; nt++)
                    mma16816(acc[mt][nt], ah, bh[nt]);
            }
        }
    }

    // ---- epilogue: bias add + fp16 store ----
    const int groupid = lane >> 2;
    const int t4      = lane & 3;
    float2 bv[8];
#pragma unroll
    for (int nt = 0; nt < 8; nt++)
        bv[nt] = *(const float2*)(bias + (size_t)e * DDIM + n0 + warp_n * 64 + nt * 8 + t4 * 2);

    __half* OutB = (WHICH == 1) ? g_h1 : g_h2;
#pragma unroll
    for (int mt = 0; mt < 4; mt++) {
        int r0 = m0 + warp_m * 64 + mt * 16 + groupid;
        int r1 = r0 + 8;
        __half* p0 = OutB + ((size_t)e * TOK + r0) * DDIM + n0 + warp_n * 64 + t4 * 2;
        __half* p1 = OutB + ((size_t)e * TOK + r1) * DDIM + n0 + warp_n * 64 + t4 * 2;
#pragma unroll
        for (int nt = 0; nt < 8; nt++) {
            if (r0 < cnt)
                *(__half2*)(p0 + nt * 8) =
                    __floats2half2_rn(acc[mt][nt][0] + bv[nt].x, acc[mt][nt][1] + bv[nt].y);
            if (r1 < cnt)
                *(__half2*)(p1 + nt * 8) =
                    __floats2half2_rn(acc[mt][nt][2] + bv[nt].x, acc[mt][nt][3] + bv[nt].y);
        }
    }
}

// ---------------------------------------------------------------------------
// 3) LN1 + relu: reads g_h1 fp16, writes fp16 into g_ah
// ---------------------------------------------------------------------------
__global__ void ln1_kernel(const float* __restrict__ w,
                           const float* __restrict__ b) {
    int gw = (blockIdx.x * blockDim.x + threadIdx.x) >> 5;
    int e   = gw >> 15;
    int pos = gw & (TOK - 1);
    if (pos >= g_cnt[e]) return;
    int lane = threadIdx.x & 31;
    const __half2* row = (const __half2*)(g_h1 + (size_t)gw * DDIM);

    float2 v[8];
    float s = 0.f;
#pragma unroll
    for (int i = 0; i < 8; i++) {
        v[i] = __half22float2(row[lane + i * 32]);
        s += v[i].x + v[i].y;
    }
#pragma unroll
    for (int o = 16; o > 0; o >>= 1) s += __shfl_xor_sync(0xffffffffu, s, o);
    float mu = s * (1.f / DDIM);

    float q = 0.f;
#pragma unroll
    for (int i = 0; i < 8; i++) {
        float dx = v[i].x - mu, dy = v[i].y - mu;
        q += dx * dx + dy * dy;
    }
#pragma unroll
    for (int o = 16; o > 0; o >>= 1) q += __shfl_xor_sync(0xffffffffu, q, o);
    float rstd = rsqrtf(q * (1.f / DDIM) + LN_EPS);

    const float* we = w + e * DDIM;
    const float* be = b + e * DDIM;
    __half* oh = g_ah + (size_t)gw * DDIM;
#pragma unroll
    for (int i = 0; i < 8; i++) {
        int d = 2 * (lane + i * 32);
        float yx = fmaxf((v[i].x - mu) * rstd * we[d] + be[d], 0.f);
        float yy = fmaxf((v[i].y - mu) * rstd * we[d + 1] + be[d + 1], 0.f);
        *(__half2*)(oh + d) = __floats2half2_rn(yx, yy);
    }
}

// ---------------------------------------------------------------------------
// 6) combine + fused LN2: warp per token; 4 fp16 rows of g_h2 (pre-LN)
// ---------------------------------------------------------------------------
__global__ void combine_kernel(const float* __restrict__ x,
                               const float* __restrict__ lnw,
                               const float* __restrict__ lnb,
                               float* __restrict__ out) {
    int gw   = (blockIdx.x * blockDim.x + threadIdx.x) >> 5;
    int lane = threadIdx.x & 31;
    const int t = gw;

    int   pr[4];
    float wt[4];
#pragma unroll
    for (int j = 0; j < 4; j++) {
        pr[j] = g_tokPair[t * 4 + j];
        wt[j] = g_tokW[t * 4 + j];
    }

    float2 v[4][8];
    float mu[4], rs[4];
#pragma unroll
    for (int r = 0; r < 4; r++) {
        const __half2* row = (const __half2*)(g_h2 + (size_t)pr[r] * DDIM);
        float s = 0.f;
#pragma unroll
        for (int i = 0; i < 8; i++) {
            v[r][i] = __half22float2(row[lane + i * 32]);
            s += v[r][i].x + v[r][i].y;
        }
#pragma unroll
        for (int o = 16; o > 0; o >>= 1) s += __shfl_xor_sync(0xffffffffu, s, o);
        mu[r] = s * (1.f / DDIM);
        float q = 0.f;
#pragma unroll
        for (int i = 0; i < 8; i++) {
            float dx = v[r][i].x - mu[r], dy = v[r][i].y - mu[r];
            q += dx * dx + dy * dy;
        }
#pragma unroll
        for (int o = 16; o > 0; o >>= 1) q += __shfl_xor_sync(0xffffffffu, q, o);
        rs[r] = rsqrtf(q * (1.f / DDIM) + LN_EPS);
    }

    const float* lw[4];
    const float* lb[4];
#pragma unroll
    for (int r = 0; r < 4; r++) {
        int e = pr[r] >> 15;           // / TOK
        lw[r] = lnw + (size_t)e * DDIM;
        lb[r] = lnb + (size_t)e * DDIM;
    }

    const float* xr = x + (size_t)t * DDIM;
    float* o_out = out + (size_t)t * DDIM;
    float* o_top = out + (size_t)BND + (size_t)t * DDIM;
    float* o_bot = out + 2 * (size_t)BND + (size_t)t * DDIM;

    float accd = 0.f;
#pragma unroll
    for (int i = 0; i < 8; i++) {
        int d = 2 * (lane + i * 32);
#pragma unroll
        for (int h = 0; h < 2; h++) {
            int dd = d + h;
            float va = h ? v[0][i].y : v[0][i].x;
            float vb = h ? v[1][i].y : v[1][i].x;
            float vc = h ? v[2][i].y : v[2][i].x;
            float vd = h ? v[3][i].y : v[3][i].x;
            float ya = (va - mu[0]) * rs[0] * lw[0][dd] + lb[0][dd];
            float yb = (vb - mu[1]) * rs[1] * lw[1][dd] + lb[1][dd];
            float yc = (vc - mu[2]) * rs[2] * lw[2][dd] + lb[2][dd];
            float yd = (vd - mu[3]) * rs[3] * lw[3][dd] + lb[3][dd];
            float top = wt[0] * ya + wt[1] * yb;
            float bot = wt[2] * yc + wt[3] * yd;
            o_top[dd] = top;
            o_bot[dd] = bot;
            o_out[dd] = top + xr[dd];
            float df = top - bot;
            accd += df * df;
        }
    }
#pragma unroll
    for (int o = 16; o > 0; o >>= 1) accd += __shfl_xor_sync(0xffffffffu, accd, o);

    __shared__ float red[8];
    if (lane == 0) red[threadIdx.x >> 5] = accd;
    __syncthreads();
    if (threadIdx.x == 0) {
        float ssum = 0.f;
        for (int i = 0; i < 8; i++) ssum += red[i];
        g_part[blockIdx.x] = ssum;
    }
}

// ---------------------------------------------------------------------------
// 7) loss
// ---------------------------------------------------------------------------
__global__ void loss_kernel(float* __restrict__ out) {
    int w = threadIdx.x >> 5, lane = threadIdx.x & 31;
    __shared__ float lred[8];
    float s = 0.f;
    for (int i = lane; i < 512; i += 32) s += g_part[w * 512 + i];
#pragma unroll
    for (int o = 16; o > 0; o >>= 1) s += __shfl_xor_sync(0xffffffffu, s, o);
    if (lane == 0) lred[w] = 1.f / (sqrtf(s) + 1e-8f);
    __syncthreads();
    if (threadIdx.x == 0) {
        float a = 0.f;
        for (int i = 0; i < 8; i++) a += lred[i];
        out[(size_t)3 * BND] = a * (1.f / 8.f);
    }
}

// ---------------------------------------------------------------------------
// launch
// ---------------------------------------------------------------------------
extern "C" void kernel_launch(void* const* d_in, const int* in_sizes, int n_in,
                              void* d_out, int out_size) {
    const float* x    = (const float*)d_in[0];
    const float* Wg   = (const float*)d_in[1];
    const float* bg   = (const float*)d_in[2];
    const float* W1   = (const float*)d_in[3];
    const float* b1   = (const float*)d_in[4];
    const float* ln1w = (const float*)d_in[5];
    const float* ln1b = (const float*)d_in[6];
    const float* W2   = (const float*)d_in[7];
    const float* b2   = (const float*)d_in[8];
    const float* ln2w = (const float*)d_in[9];
    const float* ln2b = (const float*)d_in[10];
    float* out = (float*)d_out;

    static int smem_set = 0;
    if (!smem_set) {
        cudaFuncSetAttribute(gemm_mma<1>, cudaFuncAttributeMaxDynamicSharedMemorySize, SMEM_DYN);
        cudaFuncSetAttribute(gemm_mma<2>, cudaFuncAttributeMaxDynamicSharedMemorySize, SMEM_DYN);
        smem_set = 1;
    }

    init_kernel<<<1, 32>>>();
    gating_kernel<<<TOK * 32 / 256, 256>>>(x, Wg, bg);

    dim3 wgrid(DDIM / 32, DDIM / 32, 2 * NEXP);   // merged W1+W2
    wconv_kernel<<<wgrid, dim3(32, 8)>>>(W1, W2);

    dim3 ggrid(DDIM / BN, TOK / BM, NEXP);   // (2, 256, 8)
    gemm_mma<1><<<ggrid, 256, SMEM_DYN>>>(b1);
    ln1_kernel<<<NEXP * TOK * 32 / 256, 256>>>(ln1w, ln1b);
    gemm_mma<2><<<ggrid, 256, SMEM_DYN>>>(b2);
    combine_kernel<<<TOK * 32 / 256, 256>>>(x, ln2w, ln2b, out);
    loss_kernel<<<1, 256>>>(out);
}

// round 12
// speedup vs baseline: 1.2165x; 1.0220x over previous
#include <cuda_runtime.h>
#include <cuda_fp16.h>
#include <math.h>
#include <stdint.h>

// Problem constants
#define TOK   32768          // B*N = 8*4096
#define NEXP  8
#define DDIM  512
#define BND   16777216       // TOK * DDIM
#define LN_EPS 1e-5f

// GEMM tile config (pure fp16 operands, fp32 accum)
#define BM 128
#define BN 256
#define BK 64
#define NCHUNK (DDIM / BK)   // 8
// smem stage layout (bytes): rows padded to 72 fp16 = 144B (conflict-free ldsm)
#define ROWB 144
#define A_OFF 0
#define B_OFF (BM * ROWB)                 // 18432
#define STAGE_B (B_OFF + BN * ROWB)       // 55296
#define NSTAGE 4
#define SMEM_DYN (NSTAGE * STAGE_B)       // 221184

// ---------------------------------------------------------------------------
// Scratch (__device__ globals; no allocations allowed)
// ---------------------------------------------------------------------------
__device__ int   g_cnt[NEXP];
__device__ int   g_pairTok[NEXP * TOK];
__device__ int   g_tokPair[TOK * 4];
__device__ float g_tokW[TOK * 4];
__device__ __half g_h1[(size_t)NEXP * TOK * DDIM];   // GEMM1 out (pre-LN1), fp16
__device__ __half g_h2[(size_t)NEXP * TOK * DDIM];   // GEMM2 out (pre-LN2), fp16
__device__ float g_part[4096];
__device__ __half g_xh[(size_t)TOK * DDIM];          // x fp16 (token space)
__device__ __half g_ah[(size_t)NEXP * TOK * DDIM];   // ln1 out fp16 (pair space)
__device__ __half g_w1t[(size_t)NEXP * DDIM * DDIM]; // W1^T fp16
__device__ __half g_w2t[(size_t)NEXP * DDIM * DDIM]; // W2^T fp16

// ---------------------------------------------------------------------------
// Helpers
// ---------------------------------------------------------------------------
__device__ __forceinline__ uint32_t smem_u32(const void* p) {
    uint32_t a;
    asm("{ .reg .u64 t; cvta.to.shared.u64 t, %1; cvt.u32.u64 %0, t; }" : "=r"(a) : "l"(p));
    return a;
}
__device__ __forceinline__ void cp16(uint32_t dst, const void* src) {
    asm volatile("cp.async.cg.shared.global [%0], [%1], 16;" :: "r"(dst), "l"(src));
}
#define CP_COMMIT() asm volatile("cp.async.commit_group;" ::: "memory")
#define CP_WAIT2()  asm volatile("cp.async.wait_group 2;" ::: "memory")
__device__ __forceinline__ void ldsm4(uint32_t* r, uint32_t addr) {
    asm volatile("ldmatrix.sync.aligned.m8n8.x4.shared.b16 {%0,%1,%2,%3}, [%4];"
                 : "=r"(r[0]), "=r"(r[1]), "=r"(r[2]), "=r"(r[3]) : "r"(addr));
}
__device__ __forceinline__ void mma16816(float* c, const uint32_t* a, const uint32_t* b) {
    asm volatile(
        "mma.sync.aligned.m16n8k16.row.col.f32.f16.f16.f32 "
        "{%0,%1,%2,%3}, {%4,%5,%6,%7}, {%8,%9}, {%0,%1,%2,%3};"
        : "+f"(c[0]), "+f"(c[1]), "+f"(c[2]), "+f"(c[3])
        : "r"(a[0]), "r"(a[1]), "r"(a[2]), "r"(a[3]), "r"(b[0]), "r"(b[1]));
}

// ---------------------------------------------------------------------------
// 0) zero counters
// ---------------------------------------------------------------------------
__global__ void init_kernel() {
    if (threadIdx.x < NEXP) g_cnt[threadIdx.x] = 0;
}

// ---------------------------------------------------------------------------
// 1) gating: scores + routing + x fp16 round (token space)
// ---------------------------------------------------------------------------
__global__ void gating_kernel(const float* __restrict__ x,
                              const float* __restrict__ Wg,
                              const float* __restrict__ bg) {
    int gw = (blockIdx.x * blockDim.x + threadIdx.x) >> 5;
    if (gw >= TOK) return;
    int lane = threadIdx.x & 31;
    const float* xr = x + (size_t)gw * DDIM;
    __half* xh = g_xh + (size_t)gw * DDIM;

    float s[NEXP];
#pragma unroll
    for (int e = 0; e < NEXP; e++) s[e] = 0.f;
#pragma unroll
    for (int i = 0; i < 16; i++) {
        int d = lane + i * 32;
        float xv = xr[d];
        const float* wr = Wg + d * NEXP;
#pragma unroll
        for (int e = 0; e < NEXP; e++) s[e] += xv * wr[e];
        xh[d] = __float2half_rn(xv);
    }
#pragma unroll
    for (int e = 0; e < NEXP; e++) {
#pragma unroll
        for (int o = 16; o > 0; o >>= 1)
            s[e] += __shfl_xor_sync(0xffffffffu, s[e], o);
    }
    if (lane == 0) {
#pragma unroll
        for (int e = 0; e < NEXP; e++) s[e] += bg[e];
        int i0 = 0; float v0 = s[0];
        for (int e = 1; e < NEXP; e++) if (s[e] > v0) { v0 = s[e]; i0 = e; }
        int i1 = -1; float v1 = -1e30f;
        for (int e = 0; e < NEXP; e++) if (e != i0 && s[e] > v1) { v1 = s[e]; i1 = e; }
        int j0 = 0; float u0 = s[0];
        for (int e = 1; e < NEXP; e++) if (s[e] < u0) { u0 = s[e]; j0 = e; }
        int j1 = -1; float u1 = 1e30f;
        for (int e = 0; e < NEXP; e++) if (e != j0 && s[e] < u1) { u1 = s[e]; j1 = e; }

        float et  = expf(v1 - v0);
        float wt0 = 1.f / (1.f + et);
        float wt1 = et * wt0;
        float eb  = expf(u0 - u1);
        float wb1 = 1.f / (1.f + eb);
        float wb0 = eb * wb1;

        int p;
        p = atomicAdd(&g_cnt[i0], 1);
        g_pairTok[i0 * TOK + p] = gw;
        g_tokPair[gw * 4 + 0] = i0 * TOK + p;  g_tokW[gw * 4 + 0] = wt0;
        p = atomicAdd(&g_cnt[i1], 1);
        g_pairTok[i1 * TOK + p] = gw;
        g_tokPair[gw * 4 + 1] = i1 * TOK + p;  g_tokW[gw * 4 + 1] = wt1;
        p = atomicAdd(&g_cnt[j0], 1);
        g_pairTok[j0 * TOK + p] = gw;
        g_tokPair[gw * 4 + 2] = j0 * TOK + p;  g_tokW[gw * 4 + 2] = wb0;
        p = atomicAdd(&g_cnt[j1], 1);
        g_pairTok[j1 * TOK + p] = gw;
        g_tokPair[gw * 4 + 3] = j1 * TOK + p;  g_tokW[gw * 4 + 3] = wb1;
    }
}

// ---------------------------------------------------------------------------
// 1b) weight prep (merged W1+W2): W[e][k][n] fp32 -> Wt[e][n][k] fp16
// ---------------------------------------------------------------------------
__global__ void wconv_kernel(const float* __restrict__ W1,
                             const float* __restrict__ W2) {
    __shared__ float t[32][33];
    int z = blockIdx.z;
    int e = z & 7;
    int which = z >> 3;
    const float* W = which ? W2 : W1;
    __half* T = which ? g_w2t : g_w1t;
    int kb = blockIdx.x * 32, nb = blockIdx.y * 32;
    const float* src = W + (size_t)e * DDIM * DDIM;
    int tx = threadIdx.x, ty = threadIdx.y;
#pragma unroll
    for (int r = ty; r < 32; r += 8)
        t[r][tx] = src[(size_t)(kb + r) * DDIM + nb + tx];
    __syncthreads();
#pragma unroll
    for (int r = ty; r < 32; r += 8) {
        float v = t[tx][r];  // = W[kb+tx][nb+r]
        T[((size_t)e * DDIM + (nb + r)) * DDIM + kb + tx] = __float2half_rn(v);
    }
}

// ---------------------------------------------------------------------------
// 2/4) fp16 HMMA GEMM, cp.async 4-stage pipeline, BK=64, 512 threads.
//      BM=128, BN=256; 16 warps (4 x 4), warp tile 32x64 (acc 64 regs).
//      WHICH=1: A = g_xh gathered via pairTok; out g_h1 (fp16).
//      WHICH=2: A = g_ah pair-space (ln1 out); out g_h2 (fp16).
// ---------------------------------------------------------------------------
template <int WHICH>
__global__ void __launch_bounds__(512, 1) gemm_mma(const float* __restrict__ bias) {
    const int e   = blockIdx.z;
    const int cnt = g_cnt[e];
    const int m0  = blockIdx.y * BM;
    if (m0 >= cnt) return;
    const int n0  = blockIdx.x * BN;

    extern __shared__ char dsm[];
    const uint32_t sbase = smem_u32(dsm);

    const int tid  = threadIdx.x;
    const int wid  = tid >> 5;
    const int lane = tid & 31;

    const __half* wt = (WHICH == 1) ? g_w1t : g_w2t;

    // ---- loader precompute: 6 x 16B segments per thread per stage ----
    // A: 128 rows x 8 segs (gid 0..1023); B: 256 rows x 8 segs (gid 1024..3071)
    const __half* src[6];
    uint32_t dst[6];
#pragma unroll
    for (int j = 0; j < 6; j++) {
        int gid = tid + j * 512;
        if (gid < 1024) {
            int row = gid >> 3, ks = gid & 7;
            int rr = m0 + row; if (rr > cnt - 1) rr = cnt - 1;
            if (WHICH == 1) {
                int tokid = g_pairTok[e * TOK + rr];
                src[j] = g_xh + (size_t)tokid * DDIM + ks * 8;
            } else {
                src[j] = g_ah + ((size_t)e * TOK + rr) * DDIM + ks * 8;
            }
            dst[j] = A_OFF + row * ROWB + ks * 16;
        } else {
            int idx = gid - 1024;
            int row = idx >> 3, ks = idx & 7;
            src[j] = wt + ((size_t)e * DDIM + n0 + row) * DDIM + ks * 8;
            dst[j] = B_OFF + row * ROWB + ks * 16;
        }
    }

    auto issue = [&](int chunk, int s) {
        const int k0 = chunk * BK;
        const uint32_t sb = sbase + s * STAGE_B;
#pragma unroll
        for (int j = 0; j < 6; j++) cp16(sb + dst[j], src[j] + k0);
    };

    // warp layout: warp_m = wid>>2 (32 rows), warp_n = wid&3 (64 cols)
    const int warp_m = wid >> 2;
    const int warp_n = wid & 3;
    const int l15 = lane & 15;
    const uint32_t aoff = (uint32_t)((warp_m * 32 + l15) * ROWB + (lane >> 4) * 16);
    const uint32_t boff = (uint32_t)((warp_n * 64 + (lane >> 4) * 8 + (lane & 7)) * ROWB +
                                     ((lane >> 3) & 1) * 16);

    float acc[2][8][4];
#pragma unroll
    for (int mt = 0; mt < 2; mt++)
#pragma unroll
        for (int nt = 0; nt < 8; nt++)
#pragma unroll
            for (int q = 0; q < 4; q++) acc[mt][nt][q] = 0.f;

    issue(0, 0); CP_COMMIT();
    issue(1, 1); CP_COMMIT();
    issue(2, 2); CP_COMMIT();

    for (int i = 0; i < NCHUNK; i++) {
        const int s = i % NSTAGE;
        CP_WAIT2();          // oldest outstanding group (chunk i) complete
        __syncthreads();
        if (i + 3 < NCHUNK) issue(i + 3, (i + 3) % NSTAGE);
        CP_COMMIT();

        const uint32_t sb = sbase + s * STAGE_B;
        const uint32_t aA = sb + A_OFF + aoff;
        const uint32_t bB = sb + B_OFF + boff;
#pragma unroll
        for (int k16 = 0; k16 < 4; k16++) {
            uint32_t bh[8][2];
#pragma unroll
            for (int p = 0; p < 4; p++) {
                uint32_t r4[4];
                ldsm4(r4, bB + p * 16 * ROWB + k16 * 32);
                bh[2 * p][0] = r4[0]; bh[2 * p][1] = r4[1];
                bh[2 * p + 1][0] = r4[2]; bh[2 * p + 1][1] = r4[3];
            }
#pragma unroll
            for (int mt = 0; mt < 2; mt++) {
                uint32_t ah[4];
                ldsm4(ah, aA + mt * 16 * ROWB + k16 * 32);
#pragma unroll
                for (int nt = 0; nt < 8; nt++)
                    mma16816(acc[mt][nt], ah, bh[nt]);
            }
        }
    }

    // ---- epilogue: bias add + fp16 store ----
    const int groupid = lane >> 2;
    const int t4      = lane & 3;
    float2 bv[8];
#pragma unroll
    for (int nt = 0; nt < 8; nt++)
        bv[nt] = *(const float2*)(bias + (size_t)e * DDIM + n0 + warp_n * 64 + nt * 8 + t4 * 2);

    __half* OutB = (WHICH == 1) ? g_h1 : g_h2;
#pragma unroll
    for (int mt = 0; mt < 2; mt++) {
        int r0 = m0 + warp_m * 32 + mt * 16 + groupid;
        int r1 = r0 + 8;
        __half* p0 = OutB + ((size_t)e * TOK + r0) * DDIM + n0 + warp_n * 64 + t4 * 2;
        __half* p1 = OutB + ((size_t)e * TOK + r1) * DDIM + n0 + warp_n * 64 + t4 * 2;
#pragma unroll
        for (int nt = 0; nt < 8; nt++) {
            if (r0 < cnt)
                *(__half2*)(p0 + nt * 8) =
                    __floats2half2_rn(acc[mt][nt][0] + bv[nt].x, acc[mt][nt][1] + bv[nt].y);
            if (r1 < cnt)
                *(__half2*)(p1 + nt * 8) =
                    __floats2half2_rn(acc[mt][nt][2] + bv[nt].x, acc[mt][nt][3] + bv[nt].y);
        }
    }
}

// ---------------------------------------------------------------------------
// 3) LN1 + relu: reads g_h1 fp16, writes fp16 into g_ah
// ---------------------------------------------------------------------------
__global__ void ln1_kernel(const float* __restrict__ w,
                           const float* __restrict__ b) {
    int gw = (blockIdx.x * blockDim.x + threadIdx.x) >> 5;
    int e   = gw >> 15;
    int pos = gw & (TOK - 1);
    if (pos >= g_cnt[e]) return;
    int lane = threadIdx.x & 31;
    const __half2* row = (const __half2*)(g_h1 + (size_t)gw * DDIM);

    float2 v[8];
    float s = 0.f;
#pragma unroll
    for (int i = 0; i < 8; i++) {
        v[i] = __half22float2(row[lane + i * 32]);
        s += v[i].x + v[i].y;
    }
#pragma unroll
    for (int o = 16; o > 0; o >>= 1) s += __shfl_xor_sync(0xffffffffu, s, o);
    float mu = s * (1.f / DDIM);

    float q = 0.f;
#pragma unroll
    for (int i = 0; i < 8; i++) {
        float dx = v[i].x - mu, dy = v[i].y - mu;
        q += dx * dx + dy * dy;
    }
#pragma unroll
    for (int o = 16; o > 0; o >>= 1) q += __shfl_xor_sync(0xffffffffu, q, o);
    float rstd = rsqrtf(q * (1.f / DDIM) + LN_EPS);

    const float* we = w + e * DDIM;
    const float* be = b + e * DDIM;
    __half* oh = g_ah + (size_t)gw * DDIM;
#pragma unroll
    for (int i = 0; i < 8; i++) {
        int d = 2 * (lane + i * 32);
        float yx = fmaxf((v[i].x - mu) * rstd * we[d] + be[d], 0.f);
        float yy = fmaxf((v[i].y - mu) * rstd * we[d + 1] + be[d + 1], 0.f);
        *(__half2*)(oh + d) = __floats2half2_rn(yx, yy);
    }
}

// ---------------------------------------------------------------------------
// 6) combine + fused LN2: warp per token; 4 fp16 rows of g_h2 (pre-LN)
// ---------------------------------------------------------------------------
__global__ void combine_kernel(const float* __restrict__ x,
                               const float* __restrict__ lnw,
                               const float* __restrict__ lnb,
                               float* __restrict__ out) {
    int gw   = (blockIdx.x * blockDim.x + threadIdx.x) >> 5;
    int lane = threadIdx.x & 31;
    const int t = gw;

    int   pr[4];
    float wt[4];
#pragma unroll
    for (int j = 0; j < 4; j++) {
        pr[j] = g_tokPair[t * 4 + j];
        wt[j] = g_tokW[t * 4 + j];
    }

    float2 v[4][8];
    float mu[4], rs[4];
#pragma unroll
    for (int r = 0; r < 4; r++) {
        const __half2* row = (const __half2*)(g_h2 + (size_t)pr[r] * DDIM);
        float s = 0.f;
#pragma unroll
        for (int i = 0; i < 8; i++) {
            v[r][i] = __half22float2(row[lane + i * 32]);
            s += v[r][i].x + v[r][i].y;
        }
#pragma unroll
        for (int o = 16; o > 0; o >>= 1) s += __shfl_xor_sync(0xffffffffu, s, o);
        mu[r] = s * (1.f / DDIM);
        float q = 0.f;
#pragma unroll
        for (int i = 0; i < 8; i++) {
            float dx = v[r][i].x - mu[r], dy = v[r][i].y - mu[r];
            q += dx * dx + dy * dy;
        }
#pragma unroll
        for (int o = 16; o > 0; o >>= 1) q += __shfl_xor_sync(0xffffffffu, q, o);
        rs[r] = rsqrtf(q * (1.f / DDIM) + LN_EPS);
    }

    const float* lw[4];
    const float* lb[4];
#pragma unroll
    for (int r = 0; r < 4; r++) {
        int e = pr[r] >> 15;           // / TOK
        lw[r] = lnw + (size_t)e * DDIM;
        lb[r] = lnb + (size_t)e * DDIM;
    }

    const float* xr = x + (size_t)t * DDIM;
    float* o_out = out + (size_t)t * DDIM;
    float* o_top = out + (size_t)BND + (size_t)t * DDIM;
    float* o_bot = out + 2 * (size_t)BND + (size_t)t * DDIM;

    float accd = 0.f;
#pragma unroll
    for (int i = 0; i < 8; i++) {
        int d = 2 * (lane + i * 32);
#pragma unroll
        for (int h = 0; h < 2; h++) {
            int dd = d + h;
            float va = h ? v[0][i].y : v[0][i].x;
            float vb = h ? v[1][i].y : v[1][i].x;
            float vc = h ? v[2][i].y : v[2][i].x;
            float vd = h ? v[3][i].y : v[3][i].x;
            float ya = (va - mu[0]) * rs[0] * lw[0][dd] + lb[0][dd];
            float yb = (vb - mu[1]) * rs[1] * lw[1][dd] + lb[1][dd];
            float yc = (vc - mu[2]) * rs[2] * lw[2][dd] + lb[2][dd];
            float yd = (vd - mu[3]) * rs[3] * lw[3][dd] + lb[3][dd];
            float top = wt[0] * ya + wt[1] * yb;
            float bot = wt[2] * yc + wt[3] * yd;
            o_top[dd] = top;
            o_bot[dd] = bot;
            o_out[dd] = top + xr[dd];
            float df = top - bot;
            accd += df * df;
        }
    }
#pragma unroll
    for (int o = 16; o > 0; o >>= 1) accd += __shfl_xor_sync(0xffffffffu, accd, o);

    __shared__ float red[8];
    if (lane == 0) red[threadIdx.x >> 5] = accd;
    __syncthreads();
    if (threadIdx.x == 0) {
        float ssum = 0.f;
        for (int i = 0; i < 8; i++) ssum += red[i];
        g_part[blockIdx.x] = ssum;
    }
}

// ---------------------------------------------------------------------------
// 7) loss
// ---------------------------------------------------------------------------
__global__ void loss_kernel(float* __restrict__ out) {
    int w = threadIdx.x >> 5, lane = threadIdx.x & 31;
    __shared__ float lred[8];
    float s = 0.f;
    for (int i = lane; i < 512; i += 32) s += g_part[w * 512 + i];
#pragma unroll
    for (int o = 16; o > 0; o >>= 1) s += __shfl_xor_sync(0xffffffffu, s, o);
    if (lane == 0) lred[w] = 1.f / (sqrtf(s) + 1e-8f);
    __syncthreads();
    if (threadIdx.x == 0) {
        float a = 0.f;
        for (int i = 0; i < 8; i++) a += lred[i];
        out[(size_t)3 * BND] = a * (1.f / 8.f);
    }
}

// ---------------------------------------------------------------------------
// launch
// ---------------------------------------------------------------------------
extern "C" void kernel_launch(void* const* d_in, const int* in_sizes, int n_in,
                              void* d_out, int out_size) {
    const float* x    = (const float*)d_in[0];
    const float* Wg   = (const float*)d_in[1];
    const float* bg   = (const float*)d_in[2];
    const float* W1   = (const float*)d_in[3];
    const float* b1   = (const float*)d_in[4];
    const float* ln1w = (const float*)d_in[5];
    const float* ln1b = (const float*)d_in[6];
    const float* W2   = (const float*)d_in[7];
    const float* b2   = (const float*)d_in[8];
    const float* ln2w = (const float*)d_in[9];
    const float* ln2b = (const float*)d_in[10];
    float* out = (float*)d_out;

    static int smem_set = 0;
    if (!smem_set) {
        cudaFuncSetAttribute(gemm_mma<1>, cudaFuncAttributeMaxDynamicSharedMemorySize, SMEM_DYN);
        cudaFuncSetAttribute(gemm_mma<2>, cudaFuncAttributeMaxDynamicSharedMemorySize, SMEM_DYN);
        smem_set = 1;
    }

    init_kernel<<<1, 32>>>();
    gating_kernel<<<TOK * 32 / 256, 256>>>(x, Wg, bg);

    dim3 wgrid(DDIM / 32, DDIM / 32, 2 * NEXP);   // merged W1+W2
    wconv_kernel<<<wgrid, dim3(32, 8)>>>(W1, W2);

    dim3 ggrid(DDIM / BN, TOK / BM, NEXP);   // (2, 256, 8)
    gemm_mma<1><<<ggrid, 512, SMEM_DYN>>>(b1);
    ln1_kernel<<<NEXP * TOK * 32 / 256, 256>>>(ln1w, ln1b);
    gemm_mma<2><<<ggrid, 512, SMEM_DYN>>>(b2);
    combine_kernel<<<TOK * 32 / 256, 256>>>(x, ln2w, ln2b, out);
    loss_kernel<<<1, 256>>>(out);
}